// round 14
// baseline (speedup 1.0000x reference)
#include <cuda_runtime.h>
#include <cuda_fp16.h>
#include <cstdint>

// ============================================================================
// Problem constants
// ============================================================================
#define NN   8192
#define DIMN 256
#define TMB  32            // rows per CTA (2 CTAs co-resident per SM)
#define KT   64            // j (K) per tile
#define NT   (NN / KT)     // 128 tiles

// ============================================================================
// Device scratch
// ============================================================================
__device__ float  g_h1[NN];
__device__ float  g_h2[NN];
__device__ __half g_hf[(size_t)NN * DIMN];   // h in fp16, same [N][D] layout

// ============================================================================
// SMEM layout (per CTA; 2 CTAs/SM => keep under 114 KB)
// ============================================================================
#define W_STRIDE 72        // halves per row (144 B)
#define H_STRIDE 264       // halves per row (528 B)
#define WBUF (TMB * W_STRIDE * 2)    // 4608 B
#define HBUF (KT  * H_STRIDE * 2)    // 33792 B
#define ABUF (TMB * KT * 4)          // 8192 B (adj tile 32x64 int32)
#define SOFF_W   0                        // 2 x 4608
#define SOFF_H   (2 * WBUF)               // 9216: 2 x 33792
#define SOFF_ADJ (SOFF_H + 2 * HBUF)      // 76800: 2 x 8192
#define SOFF_H1  (SOFF_ADJ + 2 * ABUF)    // 93184: 128
#define SOFF_Z   (SOFF_H1 + 128)          // 93312: 128
#define SMEMSZ   (SOFF_Z + 128)           // 93440

// ============================================================================
// Helpers
// ============================================================================
__device__ __forceinline__ uint32_t smem_u32(const void* p) {
    uint32_t a;
    asm("{ .reg .u64 t; cvta.to.shared.u64 t, %1; cvt.u32.u64 %0, t; }" : "=r"(a) : "l"(p));
    return a;
}

// weight = exp(lrelu(s) - 4); shift cancels in softmax, keeps fp16 in range
__device__ __forceinline__ float wcalc(float s, int mask) {
    float lr = fmaxf(s, 0.f) + 0.01f * fminf(s, 0.f);
    float e;
    asm("ex2.approx.ftz.f32 %0, %1;" : "=f"(e) : "f"(fmaf(lr, 1.44269504f, -5.7707801634f)));
    return mask > 0 ? e : 0.f;
}

#define MMA16816(c0, c1, c2, c3, a0, a1, a2, a3, b0, b1)                       \
    asm volatile(                                                              \
        "mma.sync.aligned.m16n8k16.row.col.f32.f16.f16.f32 "                   \
        "{%0,%1,%2,%3},{%4,%5,%6,%7},{%8,%9},{%0,%1,%2,%3};"                   \
        : "+f"(c0), "+f"(c1), "+f"(c2), "+f"(c3)                               \
        : "r"(a0), "r"(a1), "r"(a2), "r"(a3), "r"(b0), "r"(b1))

#define LDSM_X4(r0, r1, r2, r3, addr)                                          \
    asm volatile("ldmatrix.sync.aligned.m8n8.x4.shared.b16 {%0,%1,%2,%3},[%4];"\
        : "=r"(r0), "=r"(r1), "=r"(r2), "=r"(r3) : "r"(addr))

#define LDSM_X4T(r0, r1, r2, r3, addr)                                         \
    asm volatile("ldmatrix.sync.aligned.m8n8.x4.trans.shared.b16 {%0,%1,%2,%3},[%4];" \
        : "=r"(r0), "=r"(r1), "=r"(r2), "=r"(r3) : "r"(addr))

#define CP_ASYNC16(dst, src)                                                   \
    asm volatile("cp.async.cg.shared.global [%0], [%1], 16;"                   \
        :: "r"(dst), "l"(__cvta_generic_to_global(src)) : "memory")
#define CP_COMMIT()  asm volatile("cp.async.commit_group;" ::: "memory")
#define CP_WAIT0()   asm volatile("cp.async.wait_group 0;" ::: "memory")

// ============================================================================
// Fused prep kernel: h1/h2 GEMV + fp16 conversion of h (single pass over h)
// ============================================================================
__global__ void gat_prep(const float* __restrict__ h, const float* __restrict__ a) {
    int row  = blockIdx.x * 8 + (threadIdx.x >> 5);
    int lane = threadIdx.x & 31;
    const float4* hr = (const float4*)(h + (size_t)row * DIMN);
    const float4* a1 = (const float4*)a;
    const float4* a2 = (const float4*)(a + DIMN);

    float4 hv0 = hr[lane];
    float4 hv1 = hr[lane + 32];
    float4 av10 = __ldg(&a1[lane]);      float4 av11 = __ldg(&a1[lane + 32]);
    float4 av20 = __ldg(&a2[lane]);      float4 av21 = __ldg(&a2[lane + 32]);

    float s1 = hv0.x * av10.x + hv0.y * av10.y + hv0.z * av10.z + hv0.w * av10.w
             + hv1.x * av11.x + hv1.y * av11.y + hv1.z * av11.z + hv1.w * av11.w;
    float s2 = hv0.x * av20.x + hv0.y * av20.y + hv0.z * av20.z + hv0.w * av20.w
             + hv1.x * av21.x + hv1.y * av21.y + hv1.z * av21.z + hv1.w * av21.w;

    union { __half2 p[2]; uint2 u; } U0, U1;
    U0.p[0] = __floats2half2_rn(hv0.x, hv0.y);  U0.p[1] = __floats2half2_rn(hv0.z, hv0.w);
    U1.p[0] = __floats2half2_rn(hv1.x, hv1.y);  U1.p[1] = __floats2half2_rn(hv1.z, hv1.w);
    uint2* dst = (uint2*)(g_hf + (size_t)row * DIMN);
    dst[lane]      = U0.u;
    dst[lane + 32] = U1.u;

#pragma unroll
    for (int o = 16; o; o >>= 1) {
        s1 += __shfl_xor_sync(0xFFFFFFFFu, s1, o);
        s2 += __shfl_xor_sync(0xFFFFFFFFu, s2, o);
    }
    if (lane == 0) { g_h1[row] = s1; g_h2[row] = s2; }
}

// ============================================================================
// W tile compute: 8 elements per thread (row = tid>>3, cols (tid&7)*8..+7)
// ============================================================================
__device__ __forceinline__ void compute_w8(
    char* wbuf, int row, int cg,
    int4 a0, int4 a1, float4 f0, float4 f1,
    float h1v, float& zacc)
{
    float wv[8];
    wv[0] = wcalc(h1v + f0.x, a0.x); wv[1] = wcalc(h1v + f0.y, a0.y);
    wv[2] = wcalc(h1v + f0.z, a0.z); wv[3] = wcalc(h1v + f0.w, a0.w);
    wv[4] = wcalc(h1v + f1.x, a1.x); wv[5] = wcalc(h1v + f1.y, a1.y);
    wv[6] = wcalc(h1v + f1.z, a1.z); wv[7] = wcalc(h1v + f1.w, a1.w);

    union { __half2 p[4]; uint4 u; } P;
#pragma unroll
    for (int i = 0; i < 4; i++)
        P.p[i] = __floats2half2_rn(wv[2 * i], wv[2 * i + 1]);
    // accumulate ROUNDED weights so numerator/denominator stay consistent
#pragma unroll
    for (int i = 0; i < 4; i++) {
        float2 z = __half22float2(P.p[i]);
        zacc += z.x + z.y;
    }
    *(uint4*)(wbuf + row * (W_STRIDE * 2) + cg * 16) = P.u;
}

// ============================================================================
// Main fused kernel: 256 CTAs x 256 threads (8 warps), 2 CTAs/SM.
// Each CTA: 32 rows, full K. Warp tiling 1x8: 32 rows x 32 cols per warp.
// Structure is R12's (adj cp.async ring, prefetch distance 2) with halved
// CTA scope: barriers sync 8 warps; co-resident CTAs drift and interleave.
// ============================================================================
__global__ void __launch_bounds__(256, 2)
gat_main(const int* __restrict__ adj, float* __restrict__ out) {
    extern __shared__ char smem[];
    const int tid  = threadIdx.x;
    const int lane = tid & 31;
    const int wid  = tid >> 5;
    const int m0   = blockIdx.x * TMB;

    uint32_t sb = smem_u32(smem);
    float* h1s = (float*)(smem + SOFF_H1);
    float* zsh = (float*)(smem + SOFF_Z);

    // warp tile: 32 rows x 32 cols (shared rows, split cols)
    const int nbase = wid * 32;

    float acc[32];
#pragma unroll
    for (int i = 0; i < 32; i++) acc[i] = 0.f;
    float zacc = 0.f;

    const int row = tid >> 3, cg = tid & 7;   // W-compute: 32 rows x 8 col-groups

    // ldmatrix lane address components
    const int l8 = lane & 7, g01 = (lane >> 3) & 1, g2 = lane >> 4;
    const uint32_t aoff0 = (uint32_t)(     g01 * 8 + l8) * (W_STRIDE * 2) + (uint32_t)(g2 * 8) * 2;
    const uint32_t aoff1 = (uint32_t)(16 + g01 * 8 + l8) * (W_STRIDE * 2) + (uint32_t)(g2 * 8) * 2;
    const uint32_t boff  = (uint32_t)(g01 * 8 + l8) * (H_STRIDE * 2) + (uint32_t)(nbase + g2 * 8) * 2;

    // adj SMEM tile addressing: (row, cg) -> row*256 + cg*32 bytes, 2 chunks/thread
    const uint32_t a_sdst = (uint32_t)(row * 256 + cg * 32);
    const size_t   a_gsrc = (size_t)(m0 + row) * NN + (size_t)cg * 8;   // + j per tile

    // ---- prologue ----
    {
        if (tid < TMB) h1s[tid] = g_h1[m0 + tid];

        // cp.async: h tile 0 (2048 chunks / 256 thr = 8 each), adj tiles 0 and 1
#pragma unroll
        for (int it = 0; it < 8; it++) {
            int q = it * 256 + tid;
            uint32_t dst = sb + SOFF_H + (uint32_t)(q >> 5) * (H_STRIDE * 2) + (q & 31) * 16;
            CP_ASYNC16(dst, g_hf + (size_t)(q >> 5) * DIMN + (q & 31) * 8);
        }
        {
            const int* asrc0 = adj + a_gsrc;           // tile 0
            CP_ASYNC16(sb + SOFF_ADJ + a_sdst,      asrc0);
            CP_ASYNC16(sb + SOFF_ADJ + a_sdst + 16, asrc0 + 4);
            const int* asrc1 = adj + a_gsrc + KT;      // tile 1
            CP_ASYNC16(sb + SOFF_ADJ + ABUF + a_sdst,      asrc1);
            CP_ASYNC16(sb + SOFF_ADJ + ABUF + a_sdst + 16, asrc1 + 4);
        }
        CP_COMMIT();
        float4 pf0 = __ldg((const float4*)(g_h2 + cg * 8));
        float4 pf1 = __ldg((const float4*)(g_h2 + cg * 8 + 4));
        CP_WAIT0();
        __syncthreads();

        // compute W(0) from SMEM adj(0)
        const float h1v0 = h1s[row];
        int4 pa0 = *(const int4*)(smem + SOFF_ADJ + a_sdst);
        int4 pa1 = *(const int4*)(smem + SOFF_ADJ + a_sdst + 16);
        compute_w8(smem + SOFF_W, row, cg, pa0, pa1, pf0, pf1, h1v0, zacc);
        __syncthreads();
    }

    const float h1v = h1s[row];

    // ---- main loop: one sync per tile; next-tile prep interleaved ----
    for (int t = 0; t < NT; t++) {
        const int buf = t & 1;
        const uint32_t wb = sb + SOFF_W + (uint32_t)buf * WBUF;
        const uint32_t hb = sb + SOFF_H + (uint32_t)buf * HBUF;
        const bool more = (t + 1 < NT);

        int4   pa0, pa1;
        float4 pf0, pf1;
        if (more) {
            const int j1 = (t + 1) * KT;
            // cp.async h(t+1)
#pragma unroll
            for (int it = 0; it < 8; it++) {
                int q = it * 256 + tid;
                uint32_t dst = sb + SOFF_H + (uint32_t)(buf ^ 1) * HBUF +
                               (uint32_t)(q >> 5) * (H_STRIDE * 2) + (q & 31) * 16;
                CP_ASYNC16(dst, g_hf + (size_t)(j1 + (q >> 5)) * DIMN + (q & 31) * 8);
            }
            // cp.async adj(t+2) into ring slot (t&1)  [adj(t) there, consumed]
            if (t + 2 < NT) {
                const int* asrc = adj + a_gsrc + (size_t)(t + 2) * KT;
                uint32_t adst = sb + SOFF_ADJ + (uint32_t)buf * ABUF + a_sdst;
                CP_ASYNC16(adst,      asrc);
                CP_ASYNC16(adst + 16, asrc + 4);
            }
            CP_COMMIT();
            // adj(t+1) from SMEM ring slot ((t+1)&1) — landed a full tile ago
            const char* aslot = smem + SOFF_ADJ + (size_t)(buf ^ 1) * ABUF;
            pa0 = *(const int4*)(aslot + a_sdst);
            pa1 = *(const int4*)(aslot + a_sdst + 16);
            pf0 = __ldg((const float4*)(g_h2 + j1 + cg * 8));
            pf1 = __ldg((const float4*)(g_h2 + j1 + cg * 8 + 4));
        }

        // MMA over tile t (ptxas schedules the unrolled body)
#pragma unroll
        for (int ks = 0; ks < 4; ks++) {
            uint32_t a0, a1, a2, a3, a4, a5, a6, a7;
            LDSM_X4(a0, a1, a2, a3, wb + aoff0 + (uint32_t)(ks * 16) * 2);
            LDSM_X4(a4, a5, a6, a7, wb + aoff1 + (uint32_t)(ks * 16) * 2);
            uint32_t b0, b1, b2, b3, b4, b5, b6, b7;
            LDSM_X4T(b0, b1, b2, b3,
                     hb + (uint32_t)(ks * 16) * (H_STRIDE * 2) + boff);
            LDSM_X4T(b4, b5, b6, b7,
                     hb + (uint32_t)(ks * 16) * (H_STRIDE * 2) + boff + 32);
            MMA16816(acc[0],  acc[1],  acc[2],  acc[3],  a0, a1, a2, a3, b0, b1);
            MMA16816(acc[4],  acc[5],  acc[6],  acc[7],  a0, a1, a2, a3, b2, b3);
            MMA16816(acc[8],  acc[9],  acc[10], acc[11], a0, a1, a2, a3, b4, b5);
            MMA16816(acc[12], acc[13], acc[14], acc[15], a0, a1, a2, a3, b6, b7);
            MMA16816(acc[16], acc[17], acc[18], acc[19], a4, a5, a6, a7, b0, b1);
            MMA16816(acc[20], acc[21], acc[22], acc[23], a4, a5, a6, a7, b2, b3);
            MMA16816(acc[24], acc[25], acc[26], acc[27], a4, a5, a6, a7, b4, b5);
            MMA16816(acc[28], acc[29], acc[30], acc[31], a4, a5, a6, a7, b6, b7);

            if (ks == 1 && more)
                compute_w8(smem + SOFF_W + (buf ^ 1) * WBUF, row, cg,
                           pa0, pa1, pf0, pf1, h1v, zacc);
        }

        if (more) CP_WAIT0();
        __syncthreads();
    }

    // ---- epilogue: reduce Z (8 threads per row), scale, store ----
    zacc += __shfl_xor_sync(0xFFFFFFFFu, zacc, 1);
    zacc += __shfl_xor_sync(0xFFFFFFFFu, zacc, 2);
    zacc += __shfl_xor_sync(0xFFFFFFFFu, zacc, 4);
    if ((lane & 7) == 0) zsh[row] = zacc;
    __syncthreads();

    // acc idx = ms*16 + nc*8 + half*4 + c ; rows: ms*16 + (lane>>2) and +8
#pragma unroll
    for (int ms = 0; ms < 2; ms++) {
        const int   r    = ms * 16 + (lane >> 2);
        const float inv0 = 1.f / zsh[r];
        const float inv1 = 1.f / zsh[r + 8];
        const size_t gr  = (size_t)(m0 + r) * DIMN;
#pragma unroll
        for (int nc = 0; nc < 2; nc++) {
#pragma unroll
            for (int half = 0; half < 2; half++) {
                const int col = nbase + nc * 16 + half * 8 + (lane & 3) * 2;
                const int i0  = ms * 16 + nc * 8 + half * 4;
                float2 v0 = { acc[i0 + 0] * inv0, acc[i0 + 1] * inv0 };
                float2 v1 = { acc[i0 + 2] * inv1, acc[i0 + 3] * inv1 };
                *(float2*)(out + gr + col)            = v0;
                *(float2*)(out + gr + 8 * DIMN + col) = v1;
            }
        }
    }
}

// ============================================================================
// Launch
// ============================================================================
extern "C" void kernel_launch(void* const* d_in, const int* in_sizes, int n_in,
                              void* d_out, int out_size) {
    const float* h   = (const float*)d_in[0];   // [8192, 256] fp32
    const int*   adj = (const int*)d_in[1];     // [8192, 8192] int32
    const float* a   = (const float*)d_in[2];   // [512, 1] fp32
    float* out = (float*)d_out;                 // [8192, 256] fp32

    cudaFuncSetAttribute(gat_main, cudaFuncAttributeMaxDynamicSharedMemorySize, SMEMSZ);

    gat_prep<<<NN / 8, 256>>>(h, a);
    gat_main<<<NN / TMB, 256, SMEMSZ>>>(adj, out);   // 256 CTAs x 8 warps, 2/SM
}

// round 15
// speedup vs baseline: 1.1710x; 1.1710x over previous
#include <cuda_runtime.h>
#include <cuda_fp16.h>
#include <cstdint>

// ============================================================================
// Problem constants
// ============================================================================
#define NN   8192
#define DIMN 256
#define TMB  64            // rows per CTA
#define KT   64            // j (K) per tile
#define NT   (NN / KT)     // 128 tiles
#define NP   (NT / 2)      // 64 pairs (one __syncthreads per pair)

// ============================================================================
// Device scratch
// ============================================================================
__device__ float  g_h1[NN];
__device__ float  g_h2[NN];
__device__ __half g_hf[(size_t)NN * DIMN];   // h in fp16, same [N][D] layout

// ============================================================================
// SMEM layout: 4-deep W/H rings (slot = tile & 3), 2-slot self-read adj ring
// ============================================================================
#define W_STRIDE 72        // halves per row (144 B)
#define H_STRIDE 264       // halves per row (528 B)
#define WBUF (TMB * W_STRIDE * 2)    // 9216 B
#define HBUF (KT  * H_STRIDE * 2)    // 33792 B
#define ABUF (TMB * KT * 4)          // 16384 B (adj tile 64x64 int32)
#define SOFF_W   0                        // 4 x 9216   = 36864
#define SOFF_H   (4 * WBUF)               // 36864: 4 x 33792 = 135168
#define SOFF_ADJ (SOFF_H + 4 * HBUF)      // 172032: 2 x 16384 = 32768
#define SOFF_H1  (SOFF_ADJ + 2 * ABUF)    // 204800: 256
#define SOFF_Z   (SOFF_H1 + 256)          // 205056: 256
#define SMEMSZ   (SOFF_Z + 256)           // 205312 (~200.5 KB)

// ============================================================================
// Helpers
// ============================================================================
__device__ __forceinline__ uint32_t smem_u32(const void* p) {
    uint32_t a;
    asm("{ .reg .u64 t; cvta.to.shared.u64 t, %1; cvt.u32.u64 %0, t; }" : "=r"(a) : "l"(p));
    return a;
}

// weight = exp(lrelu(s) - 4); shift cancels in softmax, keeps fp16 in range
__device__ __forceinline__ float wcalc(float s, int mask) {
    float lr = fmaxf(s, 0.f) + 0.01f * fminf(s, 0.f);
    float e;
    asm("ex2.approx.ftz.f32 %0, %1;" : "=f"(e) : "f"(fmaf(lr, 1.44269504f, -5.7707801634f)));
    return mask > 0 ? e : 0.f;
}

#define MMA16816(c0, c1, c2, c3, a0, a1, a2, a3, b0, b1)                       \
    asm volatile(                                                              \
        "mma.sync.aligned.m16n8k16.row.col.f32.f16.f16.f32 "                   \
        "{%0,%1,%2,%3},{%4,%5,%6,%7},{%8,%9},{%0,%1,%2,%3};"                   \
        : "+f"(c0), "+f"(c1), "+f"(c2), "+f"(c3)                               \
        : "r"(a0), "r"(a1), "r"(a2), "r"(a3), "r"(b0), "r"(b1))

#define LDSM_X4(r0, r1, r2, r3, addr)                                          \
    asm volatile("ldmatrix.sync.aligned.m8n8.x4.shared.b16 {%0,%1,%2,%3},[%4];"\
        : "=r"(r0), "=r"(r1), "=r"(r2), "=r"(r3) : "r"(addr))

#define LDSM_X4T(r0, r1, r2, r3, addr)                                         \
    asm volatile("ldmatrix.sync.aligned.m8n8.x4.trans.shared.b16 {%0,%1,%2,%3},[%4];" \
        : "=r"(r0), "=r"(r1), "=r"(r2), "=r"(r3) : "r"(addr))

#define CP_ASYNC16(dst, src)                                                   \
    asm volatile("cp.async.cg.shared.global [%0], [%1], 16;"                   \
        :: "r"(dst), "l"(__cvta_generic_to_global(src)) : "memory")
#define CP_COMMIT()  asm volatile("cp.async.commit_group;" ::: "memory")
#define CP_WAIT0()   asm volatile("cp.async.wait_group 0;" ::: "memory")

// ============================================================================
// Fused prep kernel: h1/h2 GEMV + fp16 conversion of h (single pass over h)
// ============================================================================
__global__ void gat_prep(const float* __restrict__ h, const float* __restrict__ a) {
    int row  = blockIdx.x * 8 + (threadIdx.x >> 5);
    int lane = threadIdx.x & 31;
    const float4* hr = (const float4*)(h + (size_t)row * DIMN);
    const float4* a1 = (const float4*)a;
    const float4* a2 = (const float4*)(a + DIMN);

    float4 hv0 = hr[lane];
    float4 hv1 = hr[lane + 32];
    float4 av10 = __ldg(&a1[lane]);      float4 av11 = __ldg(&a1[lane + 32]);
    float4 av20 = __ldg(&a2[lane]);      float4 av21 = __ldg(&a2[lane + 32]);

    float s1 = hv0.x * av10.x + hv0.y * av10.y + hv0.z * av10.z + hv0.w * av10.w
             + hv1.x * av11.x + hv1.y * av11.y + hv1.z * av11.z + hv1.w * av11.w;
    float s2 = hv0.x * av20.x + hv0.y * av20.y + hv0.z * av20.z + hv0.w * av20.w
             + hv1.x * av21.x + hv1.y * av21.y + hv1.z * av21.z + hv1.w * av21.w;

    union { __half2 p[2]; uint2 u; } U0, U1;
    U0.p[0] = __floats2half2_rn(hv0.x, hv0.y);  U0.p[1] = __floats2half2_rn(hv0.z, hv0.w);
    U1.p[0] = __floats2half2_rn(hv1.x, hv1.y);  U1.p[1] = __floats2half2_rn(hv1.z, hv1.w);
    uint2* dst = (uint2*)(g_hf + (size_t)row * DIMN);
    dst[lane]      = U0.u;
    dst[lane + 32] = U1.u;

#pragma unroll
    for (int o = 16; o; o >>= 1) {
        s1 += __shfl_xor_sync(0xFFFFFFFFu, s1, o);
        s2 += __shfl_xor_sync(0xFFFFFFFFu, s2, o);
    }
    if (lane == 0) { g_h1[row] = s1; g_h2[row] = s2; }
}

// ============================================================================
// W tile compute: 8 elements per thread (row = tid>>3, cols (tid&7)*8..+7)
// ============================================================================
__device__ __forceinline__ void compute_w8(
    char* wbuf, int row, int cg,
    int4 a0, int4 a1, float4 f0, float4 f1,
    float h1v, float& zacc)
{
    float wv[8];
    wv[0] = wcalc(h1v + f0.x, a0.x); wv[1] = wcalc(h1v + f0.y, a0.y);
    wv[2] = wcalc(h1v + f0.z, a0.z); wv[3] = wcalc(h1v + f0.w, a0.w);
    wv[4] = wcalc(h1v + f1.x, a1.x); wv[5] = wcalc(h1v + f1.y, a1.y);
    wv[6] = wcalc(h1v + f1.z, a1.z); wv[7] = wcalc(h1v + f1.w, a1.w);

    union { __half2 p[4]; uint4 u; } P;
#pragma unroll
    for (int i = 0; i < 4; i++)
        P.p[i] = __floats2half2_rn(wv[2 * i], wv[2 * i + 1]);
    // accumulate ROUNDED weights so numerator/denominator stay consistent
#pragma unroll
    for (int i = 0; i < 4; i++) {
        float2 z = __half22float2(P.p[i]);
        zacc += z.x + z.y;
    }
    *(uint4*)(wbuf + row * (W_STRIDE * 2) + cg * 16) = P.u;
}

// ============================================================================
// Main fused kernel: 128 CTAs x 512 threads; each CTA 64 rows, full K.
// Pair-wise pipeline: one __syncthreads + one wait_group 0 per TWO tiles.
//   During tile t: prep W(t+2)/H(t+2) into ring slot (t+2)&3, issue adj(t+4)
//   into the self-read adj slot (t&1). Group committed per tile; the pair-end
//   wait_group 0 drains everything the NEXT pair reads (distance >= 1 pair).
// ============================================================================
__global__ void __launch_bounds__(512, 1)
gat_main(const int* __restrict__ adj, float* __restrict__ out) {
    extern __shared__ char smem[];
    const int tid  = threadIdx.x;
    const int lane = tid & 31;
    const int wid  = tid >> 5;
    const int m0   = blockIdx.x * TMB;

    uint32_t sb = smem_u32(smem);
    float* h1s = (float*)(smem + SOFF_H1);
    float* zsh = (float*)(smem + SOFF_Z);

    // warp tile: 32 rows x 32 cols (2x8 warp grid)
    const int wm = wid & 1, wn = wid >> 1;
    const int mbase = wm * 32;
    const int nbase = wn * 32;

    float acc[32];
#pragma unroll
    for (int i = 0; i < 32; i++) acc[i] = 0.f;
    float zacc = 0.f;

    const int row = tid >> 3, cg = tid & 7;   // W-compute: 64 rows x 8 col-groups

    // ldmatrix lane address components
    const int l8 = lane & 7, g01 = (lane >> 3) & 1, g2 = lane >> 4;
    const uint32_t aoff0 = (uint32_t)(mbase +      g01 * 8 + l8) * (W_STRIDE * 2) + (uint32_t)(g2 * 8) * 2;
    const uint32_t aoff1 = (uint32_t)(mbase + 16 + g01 * 8 + l8) * (W_STRIDE * 2) + (uint32_t)(g2 * 8) * 2;
    const uint32_t boff  = (uint32_t)(g01 * 8 + l8) * (H_STRIDE * 2) + (uint32_t)(nbase + g2 * 8) * 2;

    // adj addressing: (row, cg) -> row*256 + cg*32 bytes; 2 chunks per thread
    const uint32_t a_sdst = (uint32_t)(row * 256 + cg * 32);
    const size_t   a_gsrc = (size_t)(m0 + row) * NN + (size_t)cg * 8;   // + j per tile

    // ---- prologue: tiles 0,1 resident; adj(2),(3) drained ----
    {
        if (tid < TMB) h1s[tid] = g_h1[m0 + tid];
        // h(0) -> H slot 0, h(1) -> H slot 1 (4 chunks/thread per tile)
#pragma unroll
        for (int it = 0; it < 4; it++) {
            int q = it * 512 + tid;
            uint32_t o = (uint32_t)(q >> 5) * (H_STRIDE * 2) + (q & 31) * 16;
            CP_ASYNC16(sb + SOFF_H + o,        g_hf + (size_t)(q >> 5) * DIMN + (q & 31) * 8);
            CP_ASYNC16(sb + SOFF_H + HBUF + o, g_hf + (size_t)(KT + (q >> 5)) * DIMN + (q & 31) * 8);
        }
        // adj(0) -> slot 0, adj(1) -> slot 1
        {
            const int* s0 = adj + a_gsrc;
            CP_ASYNC16(sb + SOFF_ADJ + a_sdst,      s0);
            CP_ASYNC16(sb + SOFF_ADJ + a_sdst + 16, s0 + 4);
            const int* s1 = adj + a_gsrc + KT;
            CP_ASYNC16(sb + SOFF_ADJ + ABUF + a_sdst,      s1);
            CP_ASYNC16(sb + SOFF_ADJ + ABUF + a_sdst + 16, s1 + 4);
        }
        CP_COMMIT();
        float4 pf00 = __ldg((const float4*)(g_h2 + cg * 8));
        float4 pf01 = __ldg((const float4*)(g_h2 + cg * 8 + 4));
        float4 pf10 = __ldg((const float4*)(g_h2 + KT + cg * 8));
        float4 pf11 = __ldg((const float4*)(g_h2 + KT + cg * 8 + 4));
        CP_WAIT0();
        __syncthreads();

        const float h1v0 = h1s[row];
        int4 pa0 = *(const int4*)(smem + SOFF_ADJ + a_sdst);
        int4 pa1 = *(const int4*)(smem + SOFF_ADJ + a_sdst + 16);
        compute_w8(smem + SOFF_W,        row, cg, pa0, pa1, pf00, pf01, h1v0, zacc);
        pa0 = *(const int4*)(smem + SOFF_ADJ + ABUF + a_sdst);
        pa1 = *(const int4*)(smem + SOFF_ADJ + ABUF + a_sdst + 16);
        compute_w8(smem + SOFF_W + WBUF, row, cg, pa0, pa1, pf10, pf11, h1v0, zacc);

        // adj(2) -> slot 0, adj(3) -> slot 1 (own regions already consumed)
        {
            const int* s2 = adj + a_gsrc + 2 * KT;
            CP_ASYNC16(sb + SOFF_ADJ + a_sdst,      s2);
            CP_ASYNC16(sb + SOFF_ADJ + a_sdst + 16, s2 + 4);
            const int* s3 = adj + a_gsrc + 3 * KT;
            CP_ASYNC16(sb + SOFF_ADJ + ABUF + a_sdst,      s3);
            CP_ASYNC16(sb + SOFF_ADJ + ABUF + a_sdst + 16, s3 + 4);
        }
        CP_COMMIT();
        CP_WAIT0();
        __syncthreads();
    }

    const float h1v = h1s[row];

    // ---- main loop: pairs of tiles; one barrier + one wait per pair ----
    for (int p = 0; p < NP; p++) {
#pragma unroll
        for (int half = 0; half < 2; half++) {
            const int t   = 2 * p + half;
            const int buf = ((p & 1) << 1) | half;      // t & 3
            const uint32_t wb = sb + SOFF_W + (uint32_t)buf * WBUF;
            const uint32_t hb = sb + SOFF_H + (uint32_t)buf * HBUF;
            const bool prep = (t + 2 < NT);

            int4   pa0, pa1;
            float4 pf0, pf1;
            if (prep) {
                const int j2 = (t + 2) * KT;
                // h(t+2) -> H slot buf^2
#pragma unroll
                for (int it = 0; it < 4; it++) {
                    int q = it * 512 + tid;
                    uint32_t dst = sb + SOFF_H + (uint32_t)(buf ^ 2) * HBUF +
                                   (uint32_t)(q >> 5) * (H_STRIDE * 2) + (q & 31) * 16;
                    CP_ASYNC16(dst, g_hf + (size_t)(j2 + (q >> 5)) * DIMN + (q & 31) * 8);
                }
                pf0 = __ldg((const float4*)(g_h2 + j2 + cg * 8));
                pf1 = __ldg((const float4*)(g_h2 + j2 + cg * 8 + 4));
                // adj(t+2) from self-read slot (t&1) — drained at previous pair end
                const char* aslot = smem + SOFF_ADJ + (size_t)half * ABUF;
                pa0 = *(const int4*)(aslot + a_sdst);
                pa1 = *(const int4*)(aslot + a_sdst + 16);
            }

            // MMA over tile t
#pragma unroll
            for (int ks = 0; ks < 4; ks++) {
                uint32_t a0, a1, a2, a3, a4, a5, a6, a7;
                LDSM_X4(a0, a1, a2, a3, wb + aoff0 + (uint32_t)(ks * 16) * 2);
                LDSM_X4(a4, a5, a6, a7, wb + aoff1 + (uint32_t)(ks * 16) * 2);
                uint32_t b0, b1, b2, b3, b4, b5, b6, b7;
                LDSM_X4T(b0, b1, b2, b3,
                         hb + (uint32_t)(ks * 16) * (H_STRIDE * 2) + boff);
                LDSM_X4T(b4, b5, b6, b7,
                         hb + (uint32_t)(ks * 16) * (H_STRIDE * 2) + boff + 32);
                MMA16816(acc[0],  acc[1],  acc[2],  acc[3],  a0, a1, a2, a3, b0, b1);
                MMA16816(acc[4],  acc[5],  acc[6],  acc[7],  a0, a1, a2, a3, b2, b3);
                MMA16816(acc[8],  acc[9],  acc[10], acc[11], a0, a1, a2, a3, b4, b5);
                MMA16816(acc[12], acc[13], acc[14], acc[15], a0, a1, a2, a3, b6, b7);
                MMA16816(acc[16], acc[17], acc[18], acc[19], a4, a5, a6, a7, b0, b1);
                MMA16816(acc[20], acc[21], acc[22], acc[23], a4, a5, a6, a7, b2, b3);
                MMA16816(acc[24], acc[25], acc[26], acc[27], a4, a5, a6, a7, b4, b5);
                MMA16816(acc[28], acc[29], acc[30], acc[31], a4, a5, a6, a7, b6, b7);

                if (ks == 1 && prep)
                    compute_w8(smem + SOFF_W + (buf ^ 2) * WBUF, row, cg,
                               pa0, pa1, pf0, pf1, h1v, zacc);
                if (ks == 2 && t + 4 < NT) {
                    // adj(t+4) -> same self-read slot (t&1), after this tile's read
                    const int* asrc = adj + a_gsrc + (size_t)(t + 4) * KT;
                    uint32_t adst = sb + SOFF_ADJ + (uint32_t)half * ABUF + a_sdst;
                    CP_ASYNC16(adst,      asrc);
                    CP_ASYNC16(adst + 16, asrc + 4);
                }
            }
            CP_COMMIT();   // group(t) = { h(t+2), adj(t+4) } (possibly empty)
        }

        if (p + 1 < NP) {
            CP_WAIT0();        // everything pair p committed is drained
            __syncthreads();   // W/H slots for pair p+1 visible block-wide
        }
    }

    // ---- epilogue: reduce Z (8 threads per row), scale, store ----
    __syncthreads();
    zacc += __shfl_xor_sync(0xFFFFFFFFu, zacc, 1);
    zacc += __shfl_xor_sync(0xFFFFFFFFu, zacc, 2);
    zacc += __shfl_xor_sync(0xFFFFFFFFu, zacc, 4);
    if ((lane & 7) == 0) zsh[row] = zacc;
    __syncthreads();

#pragma unroll
    for (int ms = 0; ms < 2; ms++) {
        const int   r    = mbase + ms * 16 + (lane >> 2);
        const float inv0 = 1.f / zsh[r];
        const float inv1 = 1.f / zsh[r + 8];
        const size_t gr  = (size_t)(m0 + r) * DIMN;
#pragma unroll
        for (int nc = 0; nc < 2; nc++) {
#pragma unroll
            for (int half = 0; half < 2; half++) {
                const int col = nbase + nc * 16 + half * 8 + (lane & 3) * 2;
                const int i0  = ms * 16 + nc * 8 + half * 4;
                float2 v0 = { acc[i0 + 0] * inv0, acc[i0 + 1] * inv0 };
                float2 v1 = { acc[i0 + 2] * inv1, acc[i0 + 3] * inv1 };
                *(float2*)(out + gr + col)            = v0;
                *(float2*)(out + gr + 8 * DIMN + col) = v1;
            }
        }
    }
}

// ============================================================================
// Launch
// ============================================================================
extern "C" void kernel_launch(void* const* d_in, const int* in_sizes, int n_in,
                              void* d_out, int out_size) {
    const float* h   = (const float*)d_in[0];   // [8192, 256] fp32
    const int*   adj = (const int*)d_in[1];     // [8192, 8192] int32
    const float* a   = (const float*)d_in[2];   // [512, 1] fp32
    float* out = (float*)d_out;                 // [8192, 256] fp32

    cudaFuncSetAttribute(gat_main, cudaFuncAttributeMaxDynamicSharedMemorySize, SMEMSZ);

    gat_prep<<<NN / 8, 256>>>(h, a);
    gat_main<<<NN / TMB, 512, SMEMSZ>>>(adj, out);   // 128 CTAs x 16 warps
}